// round 16
// baseline (speedup 1.0000x reference)
#include <cuda_runtime.h>
#include <cuda_fp16.h>
#include <math.h>

#define N_NODES 2000
#define N_EDGES 40000
#define NBT     128      // B * Tp = 4 * 32
#define C       32
#define XPS     66       // packed x-pair stride per k (float2 units); even -> 16B-aligned rows

typedef unsigned long long u64;

// ---- f32x2 packed helpers (FFMA2 path: only reachable via PTX) ----
__device__ __forceinline__ u64 pack2(float lo, float hi) {
    u64 d; asm("mov.b64 %0, {%1, %2};" : "=l"(d) : "f"(lo), "f"(hi)); return d;
}
__device__ __forceinline__ void unpack2(u64 v, float& lo, float& hi) {
    asm("mov.b64 {%0, %1}, %2;" : "=f"(lo), "=f"(hi) : "l"(v));
}
__device__ __forceinline__ u64 fma2(u64 a, u64 b, u64 c) {
    u64 d; asm("fma.rn.f32x2 %0, %1, %2, %3;" : "=l"(d) : "l"(a), "l"(b), "l"(c)); return d;
}

// ---- scratch (no allocations; __device__ globals, zero-init at load) ----
// hw layout TRANSPOSED: [node][bt][ch] fp16 — 2 bt rows (64B each) per 128B line.
__device__ __align__(16) __half g_hw[(size_t)N_NODES * NBT * C];  // 16 MB
__device__ float  g_deg[N_NODES];     // MUST be 0 on entry (k_scan re-zeroes)
__device__ float  g_dis[N_NODES];
__device__ float  g_invdeg[N_NODES];
__device__ int    g_cnt[N_NODES];     // MUST be 0 on entry (k_scan re-zeroes)
__device__ int    g_off[N_NODES + 1];
__device__ int    g_cur[N_NODES];
__device__ __align__(8) float2 g_edge[N_EDGES];   // (src id as float bits, norm)

// Per-block int64-vs-int32 layout detection: OR of hi/odd words for this
// block's edges. int64 data (ids < 2000) => all zero. int32 => real ids.
__device__ __forceinline__ int detect_is64(const void* ei, int e, int valid) {
    int nz = 0;
    if (valid) {
        const int* w = (const int*)ei;
        nz = w[2 * e + 1] | w[2 * (N_EDGES + e) + 1];
    }
    return !__syncthreads_or(nz);
}
__device__ __forceinline__ int edge_row(const void* ei, int e, int is64) {
    return is64 ? (int)((const long long*)ei)[e] : ((const int*)ei)[e];
}
__device__ __forceinline__ int edge_col(const void* ei, int e, int is64) {
    return is64 ? (int)((const long long*)ei)[N_EDGES + e]
                : ((const int*)ei)[N_EDGES + e];
}

// ------------------------------------------------------------------
__global__ void k_deg(const void* __restrict__ ei, const float* __restrict__ ew) {
    int e = blockIdx.x * blockDim.x + threadIdx.x;
    int valid = (e < N_EDGES);
    int is64 = detect_is64(ei, e, valid);
    if (valid) {
        int c = edge_col(ei, e, is64);
        if ((unsigned)c < N_NODES) {
            atomicAdd(&g_deg[c], ew[e]);
            atomicAdd(&g_cnt[c], 1);
        }
    }
}

// single block, 256 threads: shfl-hierarchical exclusive scan + dis/invdeg.
// Consumes g_cnt/g_deg and re-zeroes them for the next kernel_launch call.
__global__ void k_scan() {
    __shared__ int wsum[8];
    int tid = threadIdx.x;
    int lane = tid & 31, wid = tid >> 5;

    int base = tid * 8;               // 256*8 = 2048 >= N_NODES
    int v[8];
    int tot = 0;
    #pragma unroll
    for (int j = 0; j < 8; j++) {
        int idx = base + j;
        int c = (idx < N_NODES) ? g_cnt[idx] : 0;
        v[j] = tot;
        tot += c;
    }
    int incl = tot;
    #pragma unroll
    for (int d = 1; d < 32; d <<= 1) {
        int n = __shfl_up_sync(0xffffffffu, incl, d);
        if (lane >= d) incl += n;
    }
    if (lane == 31) wsum[wid] = incl;
    int texcl = incl - tot;
    __syncthreads();
    if (tid == 0) {
        int run = 0;
        #pragma unroll
        for (int w = 0; w < 8; w++) { int t = wsum[w]; wsum[w] = run; run += t; }
        g_off[N_NODES] = run;
    }
    __syncthreads();
    int off = wsum[wid] + texcl;
    #pragma unroll
    for (int j = 0; j < 8; j++) {
        int idx = base + j;
        if (idx < N_NODES) {
            int o = off + v[j];
            g_off[idx] = o; g_cur[idx] = o;
            g_cnt[idx] = 0;                    // reset for next call
        }
    }
    for (int i = tid; i < N_NODES; i += 256) {
        float d = 1.0f + g_deg[i];            // self-loop weight 1
        g_dis[i]    = rsqrtf(d);
        g_invdeg[i] = 1.0f / d;               // self-loop norm = dis*dis
        g_deg[i]    = 0.0f;                   // reset for next call
    }
}

__global__ void k_fill(const void* __restrict__ ei, const float* __restrict__ ew) {
    int e = blockIdx.x * blockDim.x + threadIdx.x;
    int valid = (e < N_EDGES);
    int is64 = detect_is64(ei, e, valid);
    if (valid) {
        int r = edge_row(ei, e, is64);
        int c = edge_col(ei, e, is64);
        if ((unsigned)r < N_NODES && (unsigned)c < N_NODES) {
            int p = atomicAdd(&g_cur[c], 1);
            if ((unsigned)p < N_EDGES) {
                g_edge[p] = make_float2(__int_as_float(r),
                                        g_dis[r] * ew[e] * g_dis[c]);
            }
        }
    }
}

// ------------------------------------------------------------------
// Fused gated temporal conv + GCN weight matmul, row-pair-packed FFMA2.
// 256 threads (8 warps), tile 128 rows x 32 cols, thread = 2 row-pairs x 4
// cols. Same smem as the 128-thr version -> 3 blocks x 8 = 24 warps/SM
// (vs 15): targets the measured latency-bound regime (issue 37%, fma 39%).
__global__ void __launch_bounds__(256, 3) k_conv(
                       const float* __restrict__ x,
                       const float* __restrict__ w1, const float* __restrict__ b1,
                       const float* __restrict__ w2, const float* __restrict__ b2,
                       const float* __restrict__ gw) {
    extern __shared__ float sm[];
    float* xp0 = sm;                    // packed pairs, also reused as g-tile
    float* xp2 = sm + 32 * XPS * 2;
    float* w1a = xp2 + 32 * XPS * 2;
    float* w1b = w1a + 1024;
    float* w2a = w1b + 1024;
    float* w2b = w2a + 1024;
    float* gws = w2b + 1024;
    __shared__ __align__(16) float bs1[32];
    __shared__ __align__(16) float bs2[32];

    int bt = blockIdx.y;
    int b = bt >> 5, t = bt & 31;
    int n0 = blockIdx.x * 128;
    int nrows = N_NODES - n0; if (nrows > 128) nrows = 128;
    int tid = threadIdx.x;

    for (int i = tid; i < 1024; i += 256) {
        int o = i & 31, cc = i >> 5;
        w1a[cc * 32 + o] = w1[o * 64 + cc * 2 + 0];
        w1b[cc * 32 + o] = w1[o * 64 + cc * 2 + 1];
        w2a[cc * 32 + o] = w2[o * 64 + cc * 2 + 0];
        w2b[cc * 32 + o] = w2[o * 64 + cc * 2 + 1];
        gws[i] = gw[i];
    }
    if (tid < 32) { bs1[tid] = b1[tid]; bs2[tid] = b2[tid]; }

    const float4* x0v = (const float4*)(x + ((size_t)(b * 34 + t)     * N_NODES + n0) * C);
    const float4* x2v = (const float4*)(x + ((size_t)(b * 34 + t + 2) * N_NODES + n0) * C);
    const float4 z4 = make_float4(0.f, 0.f, 0.f, 0.f);
    for (int i = tid; i < 1024; i += 256) {
        int r = i >> 3, c4 = (i & 7) * 4;
        float4 v = (r < nrows) ? x0v[i] : z4;
        float4 u = (r < nrows) ? x2v[i] : z4;
        int fb = (r >> 1) * 2 + (r & 1);
        xp0[(c4 + 0) * (2 * XPS) + fb] = v.x;
        xp0[(c4 + 1) * (2 * XPS) + fb] = v.y;
        xp0[(c4 + 2) * (2 * XPS) + fb] = v.z;
        xp0[(c4 + 3) * (2 * XPS) + fb] = v.w;
        xp2[(c4 + 0) * (2 * XPS) + fb] = u.x;
        xp2[(c4 + 1) * (2 * XPS) + fb] = u.y;
        xp2[(c4 + 2) * (2 * XPS) + fb] = u.z;
        xp2[(c4 + 3) * (2 * XPS) + fb] = u.w;
    }
    __syncthreads();

    int cg = tid & 7;          // col group: co = cg*4
    int rt = tid >> 3;         // 0..31: 2 pairs = rows rt*4..rt*4+3
    int co = cg * 4;
    int pb = rt * 2;

    u64 acc1[2][4], acc2[2][4];
    #pragma unroll
    for (int c = 0; c < 4; c++) {
        u64 v1 = pack2(bs1[co + c], bs1[co + c]);
        u64 v2 = pack2(bs2[co + c], bs2[co + c]);
        #pragma unroll
        for (int p = 0; p < 2; p++) { acc1[p][c] = v1; acc2[p][c] = v2; }
    }

    const float4* w1a4 = (const float4*)w1a;
    const float4* w1b4 = (const float4*)w1b;
    const float4* w2a4 = (const float4*)w2a;
    const float4* w2b4 = (const float4*)w2b;

    #pragma unroll 4
    for (int k = 0; k < 32; k++) {
        // this thread's 2 x-pairs are one 16B chunk per array
        ulonglong2 la = *(const ulonglong2*)&xp0[k * (2 * XPS) + pb * 2];
        ulonglong2 lb = *(const ulonglong2*)&xp2[k * (2 * XPS) + pb * 2];
        u64 xa[2] = {la.x, la.y};
        u64 xb[2] = {lb.x, lb.y};

        float4 f1a = w1a4[k * 8 + cg];
        float4 f1b = w1b4[k * 8 + cg];
        float4 f2a = w2a4[k * 8 + cg];
        float4 f2b = w2b4[k * 8 + cg];
        u64 d1a[4] = {pack2(f1a.x, f1a.x), pack2(f1a.y, f1a.y), pack2(f1a.z, f1a.z), pack2(f1a.w, f1a.w)};
        u64 d1b[4] = {pack2(f1b.x, f1b.x), pack2(f1b.y, f1b.y), pack2(f1b.z, f1b.z), pack2(f1b.w, f1b.w)};
        u64 d2a[4] = {pack2(f2a.x, f2a.x), pack2(f2a.y, f2a.y), pack2(f2a.z, f2a.z), pack2(f2a.w, f2a.w)};
        u64 d2b[4] = {pack2(f2b.x, f2b.x), pack2(f2b.y, f2b.y), pack2(f2b.z, f2b.z), pack2(f2b.w, f2b.w)};
        #pragma unroll
        for (int p = 0; p < 2; p++)
            #pragma unroll
            for (int c = 0; c < 4; c++) {
                acc1[p][c] = fma2(xa[p], d1a[c], acc1[p][c]);
                acc1[p][c] = fma2(xb[p], d1b[c], acc1[p][c]);
                acc2[p][c] = fma2(xa[p], d2a[c], acc2[p][c]);
                acc2[p][c] = fma2(xb[p], d2b[c], acc2[p][c]);
            }
    }

    __syncthreads();
    // g = tanh(a1)*sigmoid(a2): per channel, this thread's 2 pairs = 1 STS.128
    #pragma unroll
    for (int c = 0; c < 4; c++) {
        float gv[4];
        #pragma unroll
        for (int p = 0; p < 2; p++) {
            float a0, a1v, s0, s1;
            unpack2(acc1[p][c], a0, a1v);
            unpack2(acc2[p][c], s0, s1);
            float th0 = 2.0f / (1.0f + __expf(-2.0f * a0)) - 1.0f;
            float th1 = 2.0f / (1.0f + __expf(-2.0f * a1v)) - 1.0f;
            float sg0 = 1.0f / (1.0f + __expf(-s0));
            float sg1 = 1.0f / (1.0f + __expf(-s1));
            gv[2 * p]     = th0 * sg0;
            gv[2 * p + 1] = th1 * sg1;
        }
        *(float4*)&xp0[(co + c) * (2 * XPS) + pb * 2] = make_float4(gv[0], gv[1], gv[2], gv[3]);
    }
    __syncthreads();

    u64 hacc[2][4];
    u64 z = pack2(0.0f, 0.0f);
    #pragma unroll
    for (int p = 0; p < 2; p++)
        #pragma unroll
        for (int c = 0; c < 4; c++) hacc[p][c] = z;

    const float4* gws4 = (const float4*)gws;
    #pragma unroll 4
    for (int k = 0; k < 32; k++) {
        ulonglong2 lg = *(const ulonglong2*)&xp0[k * (2 * XPS) + pb * 2];
        u64 gp[2] = {lg.x, lg.y};
        float4 fg = gws4[k * 8 + cg];
        u64 dg[4] = {pack2(fg.x, fg.x), pack2(fg.y, fg.y), pack2(fg.z, fg.z), pack2(fg.w, fg.w)};
        #pragma unroll
        for (int p = 0; p < 2; p++)
            #pragma unroll
            for (int c = 0; c < 4; c++)
                hacc[p][c] = fma2(gp[p], dg[c], hacc[p][c]);
    }

    // fp16 epilogue into TRANSPOSED layout: g_hw[(node*NBT + bt)*C + ch]
    #pragma unroll
    for (int p = 0; p < 2; p++) {
        int re = rt * 4 + 2 * p;
        float e0, o0, e1, o1, e2, o2, e3, o3;
        unpack2(hacc[p][0], e0, o0);
        unpack2(hacc[p][1], e1, o1);
        unpack2(hacc[p][2], e2, o2);
        unpack2(hacc[p][3], e3, o3);
        if (re < nrows) {
            __half2* d0 = (__half2*)&g_hw[((size_t)(n0 + re) * NBT + bt) * C + co];
            d0[0] = __floats2half2_rn(e0, e1);
            d0[1] = __floats2half2_rn(e2, e3);
        }
        if (re + 1 < nrows) {
            __half2* d1 = (__half2*)&g_hw[((size_t)(n0 + re + 1) * NBT + bt) * C + co];
            d1[0] = __floats2half2_rn(o0, o1);
            d1[1] = __floats2half2_rn(o2, o3);
        }
    }
}

// ------------------------------------------------------------------
// Gather v3 (proven R14): warp = (dst, bt-group-of-4). lanes = (4 bt x 8
// channel-quads). Transposed hw: per edge one 32-lane LDG.64 covers 256B =
// 2 lines for 4 bt (0.5 lines/edge-bt) + 1 broadcast metadata LDG.64.
__global__ void k_gather(const float* __restrict__ gb, float* __restrict__ out) {
    int gw = (blockIdx.x * blockDim.x + threadIdx.x) >> 5;
    if (gw >= N_NODES * (NBT / 4)) return;
    int lane = threadIdx.x & 31;
    int dst = gw >> 5;                    // gw / 32  (NBT/4 = 32 groups)
    int btg = gw & 31;
    int bt  = btg * 4 + (lane >> 3);      // 4 bt per warp
    int chq = lane & 7;                   // channel quad: ch = chq*4..chq*4+3
    const size_t btoff = (size_t)bt * C + chq * 4;   // within a node row-block

    float4 acc = *(const float4*)&gb[chq * 4];
    float4 acc2 = make_float4(0.f, 0.f, 0.f, 0.f);
    {
        float idg = g_invdeg[dst];
        uint2 raw = *(const uint2*)&g_hw[(size_t)dst * (NBT * C) + btoff];
        float2 v0 = __half22float2(*(__half2*)&raw.x);
        float2 v1 = __half22float2(*(__half2*)&raw.y);
        acc.x += idg * v0.x; acc.y += idg * v0.y;
        acc.z += idg * v1.x; acc.w += idg * v1.y;
    }

    int s = g_off[dst], e = g_off[dst + 1];
    int i = s;
    for (; i + 1 < e; i += 2) {
        float2 ea = g_edge[i];            // broadcast to all 32 lanes
        float2 eb = g_edge[i + 1];
        int   sa = __float_as_int(ea.x); float na = ea.y;
        int   sb = __float_as_int(eb.x); float nb = eb.y;
        uint2 ra = *(const uint2*)&g_hw[(size_t)sa * (NBT * C) + btoff];
        uint2 rb = *(const uint2*)&g_hw[(size_t)sb * (NBT * C) + btoff];
        float2 a0 = __half22float2(*(__half2*)&ra.x);
        float2 a1 = __half22float2(*(__half2*)&ra.y);
        float2 b0 = __half22float2(*(__half2*)&rb.x);
        float2 b1 = __half22float2(*(__half2*)&rb.y);
        acc.x  += na * a0.x; acc.y  += na * a0.y;
        acc.z  += na * a1.x; acc.w  += na * a1.y;
        acc2.x += nb * b0.x; acc2.y += nb * b0.y;
        acc2.z += nb * b1.x; acc2.w += nb * b1.y;
    }
    if (i < e) {
        float2 ea = g_edge[i];
        int sa = __float_as_int(ea.x); float na = ea.y;
        uint2 ra = *(const uint2*)&g_hw[(size_t)sa * (NBT * C) + btoff];
        float2 a0 = __half22float2(*(__half2*)&ra.x);
        float2 a1 = __half22float2(*(__half2*)&ra.y);
        acc.x += na * a0.x; acc.y += na * a0.y;
        acc.z += na * a1.x; acc.w += na * a1.y;
    }

    acc.x += acc2.x; acc.y += acc2.y; acc.z += acc2.z; acc.w += acc2.w;
    *(float4*)&out[((size_t)bt * N_NODES + dst) * C + chq * 4] = acc;
}

// ------------------------------------------------------------------
extern "C" void kernel_launch(void* const* d_in, const int* in_sizes, int n_in,
                              void* d_out, int out_size) {
    const float* x  = (const float*)d_in[0];
    const void*  ei = d_in[1];                 // int64 OR int32 — detected per-block
    const float* ew = (const float*)d_in[2];
    const float* w1 = (const float*)d_in[3];
    const float* b1 = (const float*)d_in[4];
    const float* w2 = (const float*)d_in[5];
    const float* b2 = (const float*)d_in[6];
    const float* gw = (const float*)d_in[7];
    const float* gb = (const float*)d_in[8];
    float* out = (float*)d_out;

    k_deg  <<<(N_EDGES + 255) / 256, 256>>>(ei, ew);
    k_scan <<<1, 256>>>();
    k_fill <<<(N_EDGES + 255) / 256, 256>>>(ei, ew);

    int smem = (2 * 32 * XPS * 2 + 5 * 1024) * (int)sizeof(float);   // 54272 B
    cudaFuncSetAttribute(k_conv, cudaFuncAttributeMaxDynamicSharedMemorySize, smem);
    dim3 grid(16, NBT);
    k_conv<<<grid, 256, smem>>>(x, w1, b1, w2, b2, gw);

    int totw = N_NODES * (NBT / 4);                  // 64000 warps
    k_gather<<<(totw * 32 + 255) / 256, 256>>>(gb, out);
}

// round 17
// speedup vs baseline: 1.1362x; 1.1362x over previous
#include <cuda_runtime.h>
#include <cuda_fp16.h>
#include <math.h>

#define N_NODES 2000
#define N_EDGES 40000
#define NBT     128      // B * Tp = 4 * 32
#define C       32
#define XPS     65       // packed x-pair stride per k (float2 units)

typedef unsigned long long u64;

// ---- f32x2 packed helpers (FFMA2 path: only reachable via PTX) ----
__device__ __forceinline__ u64 pack2(float lo, float hi) {
    u64 d; asm("mov.b64 %0, {%1, %2};" : "=l"(d) : "f"(lo), "f"(hi)); return d;
}
__device__ __forceinline__ void unpack2(u64 v, float& lo, float& hi) {
    asm("mov.b64 {%0, %1}, %2;" : "=f"(lo), "=f"(hi) : "l"(v));
}
__device__ __forceinline__ u64 fma2(u64 a, u64 b, u64 c) {
    u64 d; asm("fma.rn.f32x2 %0, %1, %2, %3;" : "=l"(d) : "l"(a), "l"(b), "l"(c)); return d;
}

// ---- scratch (no allocations; __device__ globals, zero-init at load) ----
// hw layout TRANSPOSED: [node][bt][ch] fp16 — 2 bt rows (64B each) per 128B line.
__device__ __align__(16) __half g_hw[(size_t)N_NODES * NBT * C];  // 16 MB
__device__ float  g_deg[N_NODES];     // MUST be 0 on entry (k_scan re-zeroes)
__device__ float  g_dis[N_NODES];
__device__ float  g_invdeg[N_NODES];
__device__ int    g_cnt[N_NODES];     // MUST be 0 on entry (k_scan re-zeroes)
__device__ int    g_off[N_NODES + 1];
__device__ int    g_cur[N_NODES];
__device__ __align__(8) float2 g_edge[N_EDGES];   // (src id as float bits, norm)

// Per-block int64-vs-int32 layout detection: OR of hi/odd words for this
// block's edges. int64 data (ids < 2000) => all zero. int32 => real ids.
__device__ __forceinline__ int detect_is64(const void* ei, int e, int valid) {
    int nz = 0;
    if (valid) {
        const int* w = (const int*)ei;
        nz = w[2 * e + 1] | w[2 * (N_EDGES + e) + 1];
    }
    return !__syncthreads_or(nz);
}
__device__ __forceinline__ int edge_row(const void* ei, int e, int is64) {
    return is64 ? (int)((const long long*)ei)[e] : ((const int*)ei)[e];
}
__device__ __forceinline__ int edge_col(const void* ei, int e, int is64) {
    return is64 ? (int)((const long long*)ei)[N_EDGES + e]
                : ((const int*)ei)[N_EDGES + e];
}

// ------------------------------------------------------------------
__global__ void k_deg(const void* __restrict__ ei, const float* __restrict__ ew) {
    int e = blockIdx.x * blockDim.x + threadIdx.x;
    int valid = (e < N_EDGES);
    int is64 = detect_is64(ei, e, valid);
    if (valid) {
        int c = edge_col(ei, e, is64);
        if ((unsigned)c < N_NODES) {
            atomicAdd(&g_deg[c], ew[e]);
            atomicAdd(&g_cnt[c], 1);
        }
    }
}

// single block, 256 threads: shfl-hierarchical exclusive scan + dis/invdeg.
// Consumes g_cnt/g_deg and re-zeroes them for the next kernel_launch call.
__global__ void k_scan() {
    __shared__ int wsum[8];
    int tid = threadIdx.x;
    int lane = tid & 31, wid = tid >> 5;

    int base = tid * 8;               // 256*8 = 2048 >= N_NODES
    int v[8];
    int tot = 0;
    #pragma unroll
    for (int j = 0; j < 8; j++) {
        int idx = base + j;
        int c = (idx < N_NODES) ? g_cnt[idx] : 0;
        v[j] = tot;
        tot += c;
    }
    int incl = tot;
    #pragma unroll
    for (int d = 1; d < 32; d <<= 1) {
        int n = __shfl_up_sync(0xffffffffu, incl, d);
        if (lane >= d) incl += n;
    }
    if (lane == 31) wsum[wid] = incl;
    int texcl = incl - tot;
    __syncthreads();
    if (tid == 0) {
        int run = 0;
        #pragma unroll
        for (int w = 0; w < 8; w++) { int t = wsum[w]; wsum[w] = run; run += t; }
        g_off[N_NODES] = run;
    }
    __syncthreads();
    int off = wsum[wid] + texcl;
    #pragma unroll
    for (int j = 0; j < 8; j++) {
        int idx = base + j;
        if (idx < N_NODES) {
            int o = off + v[j];
            g_off[idx] = o; g_cur[idx] = o;
            g_cnt[idx] = 0;                    // reset for next call
        }
    }
    for (int i = tid; i < N_NODES; i += 256) {
        float d = 1.0f + g_deg[i];            // self-loop weight 1
        g_dis[i]    = rsqrtf(d);
        g_invdeg[i] = 1.0f / d;               // self-loop norm = dis*dis
        g_deg[i]    = 0.0f;                   // reset for next call
    }
}

__global__ void k_fill(const void* __restrict__ ei, const float* __restrict__ ew) {
    int e = blockIdx.x * blockDim.x + threadIdx.x;
    int valid = (e < N_EDGES);
    int is64 = detect_is64(ei, e, valid);
    if (valid) {
        int r = edge_row(ei, e, is64);
        int c = edge_col(ei, e, is64);
        if ((unsigned)r < N_NODES && (unsigned)c < N_NODES) {
            int p = atomicAdd(&g_cur[c], 1);
            if ((unsigned)p < N_EDGES) {
                g_edge[p] = make_float2(__int_as_float(r),
                                        g_dis[r] * ew[e] * g_dis[c]);
            }
        }
    }
}

// ------------------------------------------------------------------
// Fused gated temporal conv + GCN weight matmul, row-pair-packed FFMA2.
// EXACT R14 configuration (proven 93.2us): 128 thr, thread = 4 pairs x 4 cols,
// XPS=65, x via LDS.64 pairs; fp16 epilogue into TRANSPOSED [node][bt][ch].
__global__ void __launch_bounds__(128, 3) k_conv(
                       const float* __restrict__ x,
                       const float* __restrict__ w1, const float* __restrict__ b1,
                       const float* __restrict__ w2, const float* __restrict__ b2,
                       const float* __restrict__ gw) {
    extern __shared__ float sm[];
    float* xp0 = sm;                    // packed pairs, also reused as g-tile
    float* xp2 = sm + 32 * XPS * 2;
    float* w1a = xp2 + 32 * XPS * 2;
    float* w1b = w1a + 1024;
    float* w2a = w1b + 1024;
    float* w2b = w2a + 1024;
    float* gws = w2b + 1024;
    __shared__ __align__(16) float bs1[32];
    __shared__ __align__(16) float bs2[32];

    int bt = blockIdx.y;
    int b = bt >> 5, t = bt & 31;
    int n0 = blockIdx.x * 128;
    int nrows = N_NODES - n0; if (nrows > 128) nrows = 128;
    int tid = threadIdx.x;

    for (int i = tid; i < 1024; i += 128) {
        int o = i & 31, cc = i >> 5;
        w1a[cc * 32 + o] = w1[o * 64 + cc * 2 + 0];
        w1b[cc * 32 + o] = w1[o * 64 + cc * 2 + 1];
        w2a[cc * 32 + o] = w2[o * 64 + cc * 2 + 0];
        w2b[cc * 32 + o] = w2[o * 64 + cc * 2 + 1];
        gws[i] = gw[i];
    }
    if (tid < 32) { bs1[tid] = b1[tid]; bs2[tid] = b2[tid]; }

    const float4* x0v = (const float4*)(x + ((size_t)(b * 34 + t)     * N_NODES + n0) * C);
    const float4* x2v = (const float4*)(x + ((size_t)(b * 34 + t + 2) * N_NODES + n0) * C);
    const float4 z4 = make_float4(0.f, 0.f, 0.f, 0.f);
    for (int i = tid; i < 1024; i += 128) {
        int r = i >> 3, c4 = (i & 7) * 4;
        float4 v = (r < nrows) ? x0v[i] : z4;
        float4 u = (r < nrows) ? x2v[i] : z4;
        int fb = (r >> 1) * 2 + (r & 1);
        xp0[(c4 + 0) * (2 * XPS) + fb] = v.x;
        xp0[(c4 + 1) * (2 * XPS) + fb] = v.y;
        xp0[(c4 + 2) * (2 * XPS) + fb] = v.z;
        xp0[(c4 + 3) * (2 * XPS) + fb] = v.w;
        xp2[(c4 + 0) * (2 * XPS) + fb] = u.x;
        xp2[(c4 + 1) * (2 * XPS) + fb] = u.y;
        xp2[(c4 + 2) * (2 * XPS) + fb] = u.z;
        xp2[(c4 + 3) * (2 * XPS) + fb] = u.w;
    }
    __syncthreads();

    int cg = tid & 7;
    int rg = tid >> 3;
    int co = cg * 4;
    int pb = rg * 4;

    u64 acc1[4][4], acc2[4][4];
    #pragma unroll
    for (int c = 0; c < 4; c++) {
        u64 v1 = pack2(bs1[co + c], bs1[co + c]);
        u64 v2 = pack2(bs2[co + c], bs2[co + c]);
        #pragma unroll
        for (int p = 0; p < 4; p++) { acc1[p][c] = v1; acc2[p][c] = v2; }
    }

    const float4* w1a4 = (const float4*)w1a;
    const float4* w1b4 = (const float4*)w1b;
    const float4* w2a4 = (const float4*)w2a;
    const float4* w2b4 = (const float4*)w2b;

    #pragma unroll 4
    for (int k = 0; k < 32; k++) {
        u64 xa[4], xb[4];
        #pragma unroll
        for (int p = 0; p < 4; p++) {
            xa[p] = *(const u64*)&xp0[k * (2 * XPS) + (pb + p) * 2];
            xb[p] = *(const u64*)&xp2[k * (2 * XPS) + (pb + p) * 2];
        }
        float4 f1a = w1a4[k * 8 + cg];
        float4 f1b = w1b4[k * 8 + cg];
        float4 f2a = w2a4[k * 8 + cg];
        float4 f2b = w2b4[k * 8 + cg];
        u64 d1a[4] = {pack2(f1a.x, f1a.x), pack2(f1a.y, f1a.y), pack2(f1a.z, f1a.z), pack2(f1a.w, f1a.w)};
        u64 d1b[4] = {pack2(f1b.x, f1b.x), pack2(f1b.y, f1b.y), pack2(f1b.z, f1b.z), pack2(f1b.w, f1b.w)};
        u64 d2a[4] = {pack2(f2a.x, f2a.x), pack2(f2a.y, f2a.y), pack2(f2a.z, f2a.z), pack2(f2a.w, f2a.w)};
        u64 d2b[4] = {pack2(f2b.x, f2b.x), pack2(f2b.y, f2b.y), pack2(f2b.z, f2b.z), pack2(f2b.w, f2b.w)};
        #pragma unroll
        for (int p = 0; p < 4; p++)
            #pragma unroll
            for (int c = 0; c < 4; c++) {
                acc1[p][c] = fma2(xa[p], d1a[c], acc1[p][c]);
                acc1[p][c] = fma2(xb[p], d1b[c], acc1[p][c]);
                acc2[p][c] = fma2(xa[p], d2a[c], acc2[p][c]);
                acc2[p][c] = fma2(xb[p], d2b[c], acc2[p][c]);
            }
    }

    __syncthreads();
    #pragma unroll
    for (int p = 0; p < 4; p++) {
        #pragma unroll
        for (int c = 0; c < 4; c++) {
            float a0, a1v, s0, s1;
            unpack2(acc1[p][c], a0, a1v);
            unpack2(acc2[p][c], s0, s1);
            float th0 = 2.0f / (1.0f + __expf(-2.0f * a0)) - 1.0f;
            float th1 = 2.0f / (1.0f + __expf(-2.0f * a1v)) - 1.0f;
            float sg0 = 1.0f / (1.0f + __expf(-s0));
            float sg1 = 1.0f / (1.0f + __expf(-s1));
            *(u64*)&xp0[(co + c) * (2 * XPS) + (pb + p) * 2] =
                pack2(th0 * sg0, th1 * sg1);
        }
    }
    __syncthreads();

    u64 hacc[4][4];
    u64 z = pack2(0.0f, 0.0f);
    #pragma unroll
    for (int p = 0; p < 4; p++)
        #pragma unroll
        for (int c = 0; c < 4; c++) hacc[p][c] = z;

    const float4* gws4 = (const float4*)gws;
    #pragma unroll 4
    for (int k = 0; k < 32; k++) {
        u64 gp[4];
        #pragma unroll
        for (int p = 0; p < 4; p++)
            gp[p] = *(const u64*)&xp0[k * (2 * XPS) + (pb + p) * 2];
        float4 fg = gws4[k * 8 + cg];
        u64 dg[4] = {pack2(fg.x, fg.x), pack2(fg.y, fg.y), pack2(fg.z, fg.z), pack2(fg.w, fg.w)};
        #pragma unroll
        for (int p = 0; p < 4; p++)
            #pragma unroll
            for (int c = 0; c < 4; c++)
                hacc[p][c] = fma2(gp[p], dg[c], hacc[p][c]);
    }

    // fp16 epilogue into TRANSPOSED layout: g_hw[(node*NBT + bt)*C + ch]
    #pragma unroll
    for (int p = 0; p < 4; p++) {
        int re = rg * 8 + 2 * p;
        float e0, o0, e1, o1, e2, o2, e3, o3;
        unpack2(hacc[p][0], e0, o0);
        unpack2(hacc[p][1], e1, o1);
        unpack2(hacc[p][2], e2, o2);
        unpack2(hacc[p][3], e3, o3);
        if (re < nrows) {
            __half2* d0 = (__half2*)&g_hw[((size_t)(n0 + re) * NBT + bt) * C + co];
            d0[0] = __floats2half2_rn(e0, e1);
            d0[1] = __floats2half2_rn(e2, e3);
        }
        if (re + 1 < nrows) {
            __half2* d1 = (__half2*)&g_hw[((size_t)(n0 + re + 1) * NBT + bt) * C + co];
            d1[0] = __floats2half2_rn(o0, o1);
            d1[1] = __floats2half2_rn(o2, o3);
        }
    }
}

// ------------------------------------------------------------------
// Gather v3 (proven R14): warp = (dst, bt-group-of-4). lanes = (4 bt x 8
// channel-quads). Transposed hw: per edge one 32-lane LDG.64 covers 256B =
// 2 lines for 4 bt (0.5 lines/edge-bt) + 1 broadcast metadata LDG.64.
__global__ void k_gather(const float* __restrict__ gb, float* __restrict__ out) {
    int gw = (blockIdx.x * blockDim.x + threadIdx.x) >> 5;
    if (gw >= N_NODES * (NBT / 4)) return;
    int lane = threadIdx.x & 31;
    int dst = gw >> 5;                    // gw / 32  (NBT/4 = 32 groups)
    int btg = gw & 31;
    int bt  = btg * 4 + (lane >> 3);      // 4 bt per warp
    int chq = lane & 7;                   // channel quad: ch = chq*4..chq*4+3
    const size_t btoff = (size_t)bt * C + chq * 4;   // within a node row-block

    float4 acc = *(const float4*)&gb[chq * 4];
    float4 acc2 = make_float4(0.f, 0.f, 0.f, 0.f);
    {
        float idg = g_invdeg[dst];
        uint2 raw = *(const uint2*)&g_hw[(size_t)dst * (NBT * C) + btoff];
        float2 v0 = __half22float2(*(__half2*)&raw.x);
        float2 v1 = __half22float2(*(__half2*)&raw.y);
        acc.x += idg * v0.x; acc.y += idg * v0.y;
        acc.z += idg * v1.x; acc.w += idg * v1.y;
    }

    int s = g_off[dst], e = g_off[dst + 1];
    int i = s;
    for (; i + 1 < e; i += 2) {
        float2 ea = g_edge[i];            // broadcast to all 32 lanes
        float2 eb = g_edge[i + 1];
        int   sa = __float_as_int(ea.x); float na = ea.y;
        int   sb = __float_as_int(eb.x); float nb = eb.y;
        uint2 ra = *(const uint2*)&g_hw[(size_t)sa * (NBT * C) + btoff];
        uint2 rb = *(const uint2*)&g_hw[(size_t)sb * (NBT * C) + btoff];
        float2 a0 = __half22float2(*(__half2*)&ra.x);
        float2 a1 = __half22float2(*(__half2*)&ra.y);
        float2 b0 = __half22float2(*(__half2*)&rb.x);
        float2 b1 = __half22float2(*(__half2*)&rb.y);
        acc.x  += na * a0.x; acc.y  += na * a0.y;
        acc.z  += na * a1.x; acc.w  += na * a1.y;
        acc2.x += nb * b0.x; acc2.y += nb * b0.y;
        acc2.z += nb * b1.x; acc2.w += nb * b1.y;
    }
    if (i < e) {
        float2 ea = g_edge[i];
        int sa = __float_as_int(ea.x); float na = ea.y;
        uint2 ra = *(const uint2*)&g_hw[(size_t)sa * (NBT * C) + btoff];
        float2 a0 = __half22float2(*(__half2*)&ra.x);
        float2 a1 = __half22float2(*(__half2*)&ra.y);
        acc.x += na * a0.x; acc.y += na * a0.y;
        acc.z += na * a1.x; acc.w += na * a1.y;
    }

    acc.x += acc2.x; acc.y += acc2.y; acc.z += acc2.z; acc.w += acc2.w;
    *(float4*)&out[((size_t)bt * N_NODES + dst) * C + chq * 4] = acc;
}

// ------------------------------------------------------------------
extern "C" void kernel_launch(void* const* d_in, const int* in_sizes, int n_in,
                              void* d_out, int out_size) {
    const float* x  = (const float*)d_in[0];
    const void*  ei = d_in[1];                 // int64 OR int32 — detected per-block
    const float* ew = (const float*)d_in[2];
    const float* w1 = (const float*)d_in[3];
    const float* b1 = (const float*)d_in[4];
    const float* w2 = (const float*)d_in[5];
    const float* b2 = (const float*)d_in[6];
    const float* gw = (const float*)d_in[7];
    const float* gb = (const float*)d_in[8];
    float* out = (float*)d_out;

    // Side stream + events: created once on the first (uncaptured correctness)
    // call; reused on the capture call so the graph records a fork/join DAG —
    // CSR prologue runs CONCURRENTLY with k_conv (they are data-independent).
    static cudaStream_t s_side = nullptr;
    static cudaEvent_t  ev_fork = nullptr, ev_join = nullptr;
    if (s_side == nullptr) {
        cudaStreamCreateWithFlags(&s_side, cudaStreamNonBlocking);
        cudaEventCreateWithFlags(&ev_fork, cudaEventDisableTiming);
        cudaEventCreateWithFlags(&ev_join, cudaEventDisableTiming);
    }

    // fork: side stream inherits main-stream ordering point
    cudaEventRecord(ev_fork, 0);
    cudaStreamWaitEvent(s_side, ev_fork, 0);

    // CSR prologue on side stream
    k_deg  <<<(N_EDGES + 255) / 256, 256, 0, s_side>>>(ei, ew);
    k_scan <<<1, 256, 0, s_side>>>();
    k_fill <<<(N_EDGES + 255) / 256, 256, 0, s_side>>>(ei, ew);

    // conv on main stream (independent of CSR)
    int smem = (2 * 32 * XPS * 2 + 5 * 1024) * (int)sizeof(float);   // 53760 B
    cudaFuncSetAttribute(k_conv, cudaFuncAttributeMaxDynamicSharedMemorySize, smem);
    dim3 grid(16, NBT);
    k_conv<<<grid, 128, smem>>>(x, w1, b1, w2, b2, gw);

    // join: gather needs both CSR and conv results
    cudaEventRecord(ev_join, s_side);
    cudaStreamWaitEvent(0, ev_join, 0);

    int totw = N_NODES * (NBT / 4);                  // 64000 warps
    k_gather<<<(totw * 32 + 255) / 256, 256>>>(gb, out);
}